// round 14
// baseline (speedup 1.0000x reference)
#include <cuda_runtime.h>
#include <cuda_bf16.h>
#include <math.h>
#include <stdint.h>

#define BATCH 128
#define NN    50
#define FDIM  1024
#define HDIM  4096
#define MROWS (BATCH*NN)
#define KCAT  (3*FDIM)          // logical 3072: A slots [a0,a0,a1], B slots [b0,b1,b0]
#define KCATA (2*FDIM)          // stored A: [a0,a1] (slot 1 re-reads slot 0)

#define PSI_OFF  0
#define PERM_OFF (BATCH*NN*NN)
#define X_OFF    (2*BATCH*NN*NN)
#define DIST_OFF (3*BATCH*NN*NN)

#define G2_SLICES 16
#define G2_KS     (HDIM / G2_SLICES)   // 256

__device__ float         g_h[(size_t)MROWS * HDIM];
__device__ float         g_P[BATCH * NN * NN];
__device__ float         g_part[(size_t)G2_SLICES * BATCH * NN * NN];
__device__ float         g_W2T[(size_t)NN * HDIM];
__device__ __nv_bfloat16 g_Acat[(size_t)MROWS * KCATA];
__device__ __nv_bfloat16 g_Bcat[(size_t)HDIM * KCAT];

__device__ __forceinline__ uint32_t smem_u32(const void* p) {
    uint32_t a;
    asm("{ .reg .u64 t; cvta.to.shared.u64 t, %1; cvt.u32.u64 %0, t; }" : "=r"(a) : "l"(p));
    return a;
}
#define SW128(o) ((o) ^ (((o) >> 3) & 0x70))
#define CPA16(dst, src) asm volatile("cp.async.cg.shared.global [%0], [%1], 16;" :: "r"(dst), "l"(src) : "memory")
#define CPA_COMMIT()    asm volatile("cp.async.commit_group;" ::: "memory")
#define CPA_WAIT1()     asm volatile("cp.async.wait_group 1;" ::: "memory")

__device__ __forceinline__ void ldm_x4(uint32_t* r, uint32_t addr) {
    asm volatile("ldmatrix.sync.aligned.m8n8.x4.shared.b16 {%0,%1,%2,%3}, [%4];"
        : "=r"(r[0]), "=r"(r[1]), "=r"(r[2]), "=r"(r[3]) : "r"(addr));
}
__device__ __forceinline__ void mma_bf16(float* d, const uint32_t* a, const uint32_t* b) {
    asm volatile("mma.sync.aligned.m16n8k16.row.col.f32.bf16.bf16.f32 "
        "{%0,%1,%2,%3}, {%4,%5,%6,%7}, {%8,%9}, {%0,%1,%2,%3};"
        : "+f"(d[0]), "+f"(d[1]), "+f"(d[2]), "+f"(d[3])
        : "r"(a[0]), "r"(a[1]), "r"(a[2]), "r"(a[3]), "r"(b[0]), "r"(b[1]));
}

// A chunk remap: logical chunk c (of 48, 64 elems each) -> stored chunk
__device__ __forceinline__ int a_chunk(int c) {
    return (c & 15) + ((c >= 32) ? 16 : 0);
}

// ---------------- split kernels (2-term bf16 split) ----------------
__global__ __launch_bounds__(256) void split_x_kernel(const float* __restrict__ x, __nv_bfloat16* __restrict__ A) {
    int idx = blockIdx.x * 256 + threadIdx.x;
    float a = x[idx];
    __nv_bfloat16 h0 = __float2bfloat16(a);
    __nv_bfloat16 h1 = __float2bfloat16(a - __bfloat162float(h0));
    __nv_bfloat16* row = A + (size_t)(idx >> 10) * KCATA + (idx & 1023);
    row[0] = h0; row[1024] = h1;
}
__global__ __launch_bounds__(256) void split_w_kernel(const float* __restrict__ W1, __nv_bfloat16* __restrict__ B) {
    __shared__ __nv_bfloat16 t0[32][33], t1[32][33];
    const int tx = threadIdx.x, ty = threadIdx.y;   // (32,8)
    const int n0 = blockIdx.x * 32, k0 = blockIdx.y * 32;
#pragma unroll
    for (int i = 0; i < 4; i++) {
        int k = ty + i * 8;
        float w = W1[(size_t)(k0 + k) * HDIM + n0 + tx];
        __nv_bfloat16 h0 = __float2bfloat16(w);
        t0[k][tx] = h0;
        t1[k][tx] = __float2bfloat16(w - __bfloat162float(h0));
    }
    __syncthreads();
#pragma unroll
    for (int i = 0; i < 4; i++) {
        int n = ty + i * 8;
        __nv_bfloat16 b0 = t0[tx][n], b1 = t1[tx][n];
        __nv_bfloat16* row = B + (size_t)(n0 + n) * KCAT + k0 + tx;
        row[0] = b0; row[1024] = b1; row[2048] = b0;
    }
}
// W2 [4096,50] -> W2T [50,4096]
__global__ __launch_bounds__(256) void w2t_kernel(const float* __restrict__ W2, float* __restrict__ W2T) {
    int idx = blockIdx.x * 256 + threadIdx.x;       // < 50*4096
    int c = idx >> 12, k = idx & 4095;
    W2T[idx] = W2[(size_t)k * NN + c];
}

// ---------------- GEMM1: mma.sync bf16, CTA 128x128, warp tile 64x64 -------
// 4 warps (2x2), 128 threads, 3 stages, 2 CTA/SM (256 thr/SM -> 256-reg cap).
// 8 LDSM per 32 HMMA: 1/3 less smem read traffic than the 64x32 tiling.
#define G1_STAGES 3
#define G1_BKE    64
#define G1_KIT    (KCAT / G1_BKE)   // 48
#define G1_STB    32768             // A 16KB + B 16KB per stage
#define G1_SMEM   (G1_STAGES * G1_STB)

__global__ __launch_bounds__(128, 2) void gemm1_mma_kernel(
    const __nv_bfloat16* __restrict__ A, const __nv_bfloat16* __restrict__ B,
    const float* __restrict__ bias, float* __restrict__ C)
{
    extern __shared__ char sm[];
    const uint32_t sb = smem_u32(sm);
    const int tid = threadIdx.x, lane = tid & 31, wid = tid >> 5;
    const int m0 = blockIdx.x * 128, n0 = blockIdx.y * 128;
    const int wm = wid >> 1, wn = wid & 1;     // 2 (m) x 2 (n)

    // producer: thread tid loads full A row tid and full B row tid (8 segs each)
    const __nv_bfloat16* Ag = A + (size_t)(m0 + tid) * KCATA;
    const __nv_bfloat16* Bg = B + (size_t)(n0 + tid) * KCAT;
    uint32_t swo[8];
#pragma unroll
    for (int j = 0; j < 8; j++) swo[j] = SW128((uint32_t)(tid * 128 + j * 16));

#define G1_ISSUE(it) do { \
    const int st_ = (it) % G1_STAGES; \
    const int kea_ = a_chunk(it) * G1_BKE; const int keb_ = (it) * G1_BKE; \
    const uint32_t so_ = sb + st_ * G1_STB; \
    _Pragma("unroll") \
    for (int j = 0; j < 8; j++) { \
        CPA16(so_ + swo[j],         Ag + kea_ + j * 8); \
        CPA16(so_ + 16384 + swo[j], Bg + keb_ + j * 8); \
    } } while (0)

    G1_ISSUE(0); CPA_COMMIT();
    G1_ISSUE(1); CPA_COMMIT();

    float acc[4][8][4];
#pragma unroll
    for (int i = 0; i < 4; i++)
#pragma unroll
        for (int j = 0; j < 8; j++)
#pragma unroll
            for (int q = 0; q < 4; q++) acc[i][j][q] = 0.f;

    const int a_row = wm * 64 + (lane & 7) + 8 * ((lane >> 3) & 1);
    const uint32_t a_kb = (lane >> 4) * 16;
    const int b_row = wn * 64 + (lane & 7) + 8 * (lane >> 4);
    const uint32_t b_kb = ((lane >> 3) & 1) * 16;

    for (int it = 0; it < G1_KIT; it++) {
        CPA_WAIT1();
        __syncthreads();
        if (it + 2 < G1_KIT) G1_ISSUE(it + 2);
        CPA_COMMIT();

        const uint32_t ao = sb + (it % G1_STAGES) * G1_STB;
        const uint32_t bo = ao + 16384;
#pragma unroll
        for (int kk = 0; kk < 4; kk++) {
            uint32_t af[4][4], bf[4][4];
#pragma unroll
            for (int mt = 0; mt < 4; mt++) {
                uint32_t o = (uint32_t)(a_row + mt * 16) * 128 + kk * 32 + a_kb;
                ldm_x4(af[mt], ao + SW128(o));
            }
#pragma unroll
            for (int np = 0; np < 4; np++) {
                uint32_t o = (uint32_t)(b_row + np * 16) * 128 + kk * 32 + b_kb;
                ldm_x4(bf[np], bo + SW128(o));
            }
#pragma unroll
            for (int mt = 0; mt < 4; mt++)
#pragma unroll
                for (int nt = 0; nt < 8; nt++)
                    mma_bf16(acc[mt][nt], af[mt], &bf[nt >> 1][(nt & 1) * 2]);
        }
        __syncthreads();   // load/compute phase alignment (R11: removal = 2x slower)
    }

    const int erow = lane >> 2, ecol = (lane & 3) * 2;
#pragma unroll
    for (int mt = 0; mt < 4; mt++) {
        const int r0 = m0 + wm * 64 + mt * 16 + erow;
#pragma unroll
        for (int nt = 0; nt < 8; nt++) {
            const int c = n0 + wn * 64 + nt * 8 + ecol;
            float2 bb = *(const float2*)(bias + c);
            float v0 = acc[mt][nt][0] + bb.x, v1 = acc[mt][nt][1] + bb.y;
            float v2 = acc[mt][nt][2] + bb.x, v3 = acc[mt][nt][3] + bb.y;
            float2 o0 = { v0 > 0.f ? v0 : 0.01f * v0, v1 > 0.f ? v1 : 0.01f * v1 };
            float2 o1 = { v2 > 0.f ? v2 : 0.01f * v2, v3 > 0.f ? v3 : 0.01f * v3 };
            *(float2*)(C + (size_t)r0 * HDIM + c) = o0;
            *(float2*)(C + (size_t)(r0 + 8) * HDIM + c) = o1;
        }
    }
#undef G1_ISSUE
}

// ---------------- GEMM2 split-K: grid (128 batches, 16 slices) -------------
__global__ __launch_bounds__(128) void g2split_kernel(
    const float* __restrict__ h, const float* __restrict__ W2T,
    float* __restrict__ part)
{
    __shared__ float hs[NN][68];
    __shared__ float ws[NN][68];
    const int b = blockIdx.x, s = blockIdx.y, tid = threadIdx.x;
    const int kbase = s * G2_KS;
    const float* hb = h + (size_t)b * NN * HDIM + kbase;

    const int r0 = (tid / 10) * 5, c0 = (tid % 10) * 5;   // tid<100
    float acc[5][5];
#pragma unroll
    for (int i = 0; i < 5; i++)
#pragma unroll
        for (int j = 0; j < 5; j++) acc[i][j] = 0.f;

    for (int kc = 0; kc < G2_KS; kc += 64) {
        __syncthreads();
        for (int idx = tid; idx < NN * 16; idx += 128) {
            int r = idx >> 4, q = idx & 15;
            *(float4*)&hs[r][q * 4] = *(const float4*)(hb + (size_t)r * HDIM + kc + q * 4);
            *(float4*)&ws[r][q * 4] = *(const float4*)(W2T + (size_t)r * HDIM + kbase + kc + q * 4);
        }
        __syncthreads();
        if (tid < 100) {
#pragma unroll
            for (int k = 0; k < 64; k += 4) {
                float4 a[5];
#pragma unroll
                for (int i = 0; i < 5; i++) a[i] = *(const float4*)&hs[r0 + i][k];
#pragma unroll
                for (int j = 0; j < 5; j++) {
                    float4 w = *(const float4*)&ws[c0 + j][k];
#pragma unroll
                    for (int i = 0; i < 5; i++) {
                        acc[i][j] = fmaf(a[i].x, w.x, acc[i][j]);
                        acc[i][j] = fmaf(a[i].y, w.y, acc[i][j]);
                        acc[i][j] = fmaf(a[i].z, w.z, acc[i][j]);
                        acc[i][j] = fmaf(a[i].w, w.w, acc[i][j]);
                    }
                }
            }
        }
    }
    if (tid < 100) {
        float* pp = part + ((size_t)s * BATCH + b) * NN * NN;
#pragma unroll
        for (int i = 0; i < 5; i++)
#pragma unroll
            for (int j = 0; j < 5; j++)
                pp[(r0 + i) * NN + c0 + j] = acc[i][j];
    }
}

// ---------------- Reduce partials + bias/leaky/exp + Sinkhorn --------------
__global__ __launch_bounds__(256) void sinkreduce_kernel(
    const float* __restrict__ part, const float* __restrict__ b2,
    float* __restrict__ P, float* __restrict__ out)
{
    __shared__ float sp[NN * NN];
    const int b = blockIdx.x, tid = threadIdx.x;

    for (int i = tid; i < NN * NN; i += 256) {
        float m = 0.f;
#pragma unroll
        for (int s = 0; s < G2_SLICES; s++)
            m += part[((size_t)s * BATCH + b) * NN * NN + i];
        m += b2[i % NN];
        m = (m > 0.f) ? m : 0.01f * m;
        sp[i] = expf(m);
    }
    __syncthreads();

    const int warp = tid >> 5, lane = tid & 31;
    for (int it = 0; it < 5; it++) {
        for (int i = warp; i < NN; i += 8) {
            float v0 = sp[i * NN + lane];
            float v1 = (lane + 32 < NN) ? sp[i * NN + lane + 32] : 0.f;
            float s = v0 + v1;
#pragma unroll
            for (int o = 16; o; o >>= 1) s += __shfl_xor_sync(~0u, s, o);
            sp[i * NN + lane] = v0 / s;
            if (lane + 32 < NN) sp[i * NN + lane + 32] = v1 / s;
        }
        __syncthreads();
        for (int j = warp; j < NN; j += 8) {
            float v0 = sp[lane * NN + j];
            float v1 = (lane + 32 < NN) ? sp[(lane + 32) * NN + j] : 0.f;
            float s = v0 + v1;
#pragma unroll
            for (int o = 16; o; o >>= 1) s += __shfl_xor_sync(~0u, s, o);
            sp[lane * NN + j] = v0 / s;
            if (lane + 32 < NN) sp[(lane + 32) * NN + j] = v1 / s;
        }
        __syncthreads();
    }
    float* psi_out = out + PSI_OFF + (size_t)b * NN * NN;
    float* x_out   = out + X_OFF   + (size_t)b * NN * NN;
    float* Pb      = P + (size_t)b * NN * NN;
    for (int i = tid; i < NN * NN; i += 256) {
        float v = sp[i];
        Pb[i] = v; psi_out[i] = v; x_out[i] = v;
    }
}

// ---------------- Hungarian v2: deferred potentials, register state --------
__device__ __forceinline__ unsigned long long dsort(double d) {
    long long b = __double_as_longlong(d);
    return (b < 0) ? ~(unsigned long long)b
                   : ((unsigned long long)b | 0x8000000000000000ull);
}

__global__ __launch_bounds__(32) void hungarian_kernel(const float* __restrict__ P, float* __restrict__ out) {
    __shared__ float  sc[NN * NN];
    __shared__ double u_sh[NN + 1];
    __shared__ int    rtc[NN];
    const int b = blockIdx.x, lane = threadIdx.x;
    const double BIG = 1e18;
    const float* Pb = P + (size_t)b * NN * NN;

    for (int i = lane; i < NN * NN; i += 32) sc[i] = Pb[i];
    if (lane <= NN / 2) { u_sh[lane] = 0.0; u_sh[lane + 25] = 0.0; }
    double v0 = 0.0, v1 = 0.0;
    int p0 = 0, p1 = 0;
    const bool has1 = (lane < 18);
    __syncwarp();

    for (int i = 1; i <= NN; i++) {
        bool used0 = false, used1 = !has1;
        double duse0 = 0.0, duse1 = 0.0;
        int way0 = 0, way1 = 0;
        double D = 0.0;
        int j0 = 0;

        while (true) {
            if (j0) {
                if (j0 <= 32) { if (lane == j0 - 1) { used0 = true; duse0 = D; } }
                else          { if (lane == j0 - 33) { used1 = true; duse1 = D; } }
            }
            int i0;
            if (j0 == 0) i0 = i;
            else {
                int pa = __shfl_sync(~0u, p0, (j0 - 1) & 31);
                int pb = __shfl_sync(~0u, p1, (j0 - 33) & 31);
                i0 = (j0 <= 32) ? pa : pb;
            }
            const double ub = u_sh[i0];
            const float* row = sc + (i0 - 1) * NN;
            double c0d = used0 ? BIG : (-(double)row[lane] - ub - v0);
            double c1d = used1 ? BIG : (-(double)row[lane + 32] - ub - v1);

            unsigned long long k0 = (dsort(c0d) & ~63ull) | (unsigned)(lane + 1);
            unsigned long long k1 = (dsort(c1d) & ~63ull) | (unsigned)(lane + 33);
            unsigned long long km = (k0 < k1) ? k0 : k1;
            unsigned hi = (unsigned)(km >> 32);
            unsigned mh = __reduce_min_sync(~0u, hi);
            unsigned lo = (hi == mh) ? (unsigned)km : 0xFFFFFFFFu;
            unsigned ml = __reduce_min_sync(~0u, lo);
            const int j1 = ml & 63;

            double d0 = __shfl_sync(~0u, c0d, (j1 - 1) & 31);
            double d1 = __shfl_sync(~0u, c1d, (j1 - 33) & 31);
            D += (j1 <= 32) ? d0 : d1;

            if (j1 <= 32) { if (lane == j1 - 1) way0 = j0; }
            else          { if (lane == j1 - 33) way1 = j0; }

            int q0 = __shfl_sync(~0u, p0, (j1 - 1) & 31);
            int q1 = __shfl_sync(~0u, p1, (j1 - 33) & 31);
            const int pj1 = (j1 <= 32) ? q0 : q1;
            j0 = j1;
            if (pj1 == 0) break;
        }

        if (used0) { double amt = D - duse0; v0 -= amt; u_sh[p0] += amt; }
        if (has1 && used1) { double amt = D - duse1; v1 -= amt; u_sh[p1] += amt; }
        if (lane == 0) u_sh[i] += D;
        __syncwarp();

        int j = j0;
        while (j) {
            int wa = __shfl_sync(~0u, way0, (j - 1) & 31);
            int wb = __shfl_sync(~0u, way1, (j - 33) & 31);
            int jn = (j <= 32) ? wa : wb;
            int pn;
            if (jn == 0) pn = i;
            else {
                int qa = __shfl_sync(~0u, p0, (jn - 1) & 31);
                int qb = __shfl_sync(~0u, p1, (jn - 33) & 31);
                pn = (jn <= 32) ? qa : qb;
            }
            if (j <= 32) { if (lane == j - 1) p0 = pn; }
            else         { if (lane == j - 33) p1 = pn; }
            j = jn;
        }
    }

    if (p0 > 0) rtc[p0 - 1] = lane;
    if (has1 && p1 > 0) rtc[p1 - 1] = lane + 32;
    __syncwarp();

    float* pb = out + PERM_OFF + (size_t)b * NN * NN;
    for (int i = lane; i < NN * NN; i += 32) pb[i] = 0.f;
    __syncwarp();
    if (lane == 0) {
        float dsum = 0.f;
        for (int r = 0; r < NN; r++) { int c = rtc[r]; pb[r * NN + c] = 1.0f; dsum += sc[r * NN + c]; }
        out[DIST_OFF + b] = dsum / (float)NN;
    }
}

// ---------------------------------------------------------------------------
extern "C" void kernel_launch(void* const* d_in, const int* in_sizes, int n_in,
                              void* d_out, int out_size)
{
    (void)in_sizes; (void)n_in; (void)out_size;
    const float* x  = (const float*)d_in[0];
    const float* W1 = (const float*)d_in[1];
    const float* b1 = (const float*)d_in[2];
    const float* W2 = (const float*)d_in[3];
    const float* b2 = (const float*)d_in[4];
    float* out = (float*)d_out;

    float* h;   cudaGetSymbolAddress((void**)&h,   g_h);
    float* P;   cudaGetSymbolAddress((void**)&P,   g_P);
    float* pt;  cudaGetSymbolAddress((void**)&pt,  g_part);
    float* w2t; cudaGetSymbolAddress((void**)&w2t, g_W2T);
    __nv_bfloat16* Ac; cudaGetSymbolAddress((void**)&Ac, g_Acat);
    __nv_bfloat16* Bc; cudaGetSymbolAddress((void**)&Bc, g_Bcat);

    cudaFuncSetAttribute(gemm1_mma_kernel, cudaFuncAttributeMaxDynamicSharedMemorySize, G1_SMEM);

    split_x_kernel<<<MROWS * FDIM / 256, 256>>>(x, Ac);
    split_w_kernel<<<dim3(HDIM / 32, FDIM / 32), dim3(32, 8)>>>(W1, Bc);
    w2t_kernel<<<NN * HDIM / 256, 256>>>(W2, w2t);
    gemm1_mma_kernel<<<dim3(MROWS / 128, HDIM / 128), 128, G1_SMEM>>>(Ac, Bc, b1, h);
    g2split_kernel<<<dim3(BATCH, G2_SLICES), 128>>>(h, w2t, pt);
    sinkreduce_kernel<<<BATCH, 256>>>(pt, b2, P, out);
    hungarian_kernel<<<BATCH, 32>>>(P, out);
}

// round 15
// speedup vs baseline: 1.2987x; 1.2987x over previous
#include <cuda_runtime.h>
#include <cuda_bf16.h>
#include <math.h>
#include <stdint.h>

#define BATCH 128
#define NN    50
#define FDIM  1024
#define HDIM  4096
#define MROWS (BATCH*NN)
#define KCAT  (3*FDIM)          // logical 3072: A slots [a0,a0,a1], B slots [b0,b1,b0]
#define KCATA (2*FDIM)          // stored A: [a0,a1]

#define PSI_OFF  0
#define PERM_OFF (BATCH*NN*NN)
#define X_OFF    (2*BATCH*NN*NN)
#define DIST_OFF (3*BATCH*NN*NN)

#define G2_SLICES 32            // one per gemm1 n-tile (128 hidden cols each)

__device__ float         g_P[BATCH * NN * NN];
__device__ float         g_part[(size_t)G2_SLICES * MROWS * NN];   // 41 MB
__device__ float         g_W2T[(size_t)NN * HDIM];
__device__ __nv_bfloat16 g_Acat[(size_t)MROWS * KCATA];
__device__ __nv_bfloat16 g_Bcat[(size_t)HDIM * KCAT];

__device__ __forceinline__ uint32_t smem_u32(const void* p) {
    uint32_t a;
    asm("{ .reg .u64 t; cvta.to.shared.u64 t, %1; cvt.u32.u64 %0, t; }" : "=r"(a) : "l"(p));
    return a;
}
#define SW128(o) ((o) ^ (((o) >> 3) & 0x70))
#define CPA16(dst, src) asm volatile("cp.async.cg.shared.global [%0], [%1], 16;" :: "r"(dst), "l"(src) : "memory")
#define CPA_COMMIT()    asm volatile("cp.async.commit_group;" ::: "memory")
#define CPA_WAIT1()     asm volatile("cp.async.wait_group 1;" ::: "memory")

__device__ __forceinline__ void ldm_x4(uint32_t* r, uint32_t addr) {
    asm volatile("ldmatrix.sync.aligned.m8n8.x4.shared.b16 {%0,%1,%2,%3}, [%4];"
        : "=r"(r[0]), "=r"(r[1]), "=r"(r[2]), "=r"(r[3]) : "r"(addr));
}
__device__ __forceinline__ void mma_bf16(float* d, const uint32_t* a, const uint32_t* b) {
    asm volatile("mma.sync.aligned.m16n8k16.row.col.f32.bf16.bf16.f32 "
        "{%0,%1,%2,%3}, {%4,%5,%6,%7}, {%8,%9}, {%0,%1,%2,%3};"
        : "+f"(d[0]), "+f"(d[1]), "+f"(d[2]), "+f"(d[3])
        : "r"(a[0]), "r"(a[1]), "r"(a[2]), "r"(a[3]), "r"(b[0]), "r"(b[1]));
}

__device__ __forceinline__ int a_chunk(int c) {
    return (c & 15) + ((c >= 32) ? 16 : 0);
}

// ---------------- split kernels (2-term bf16 split) ----------------
__global__ __launch_bounds__(256) void split_x_kernel(const float* __restrict__ x, __nv_bfloat16* __restrict__ A) {
    int idx = blockIdx.x * 256 + threadIdx.x;
    float a = x[idx];
    __nv_bfloat16 h0 = __float2bfloat16(a);
    __nv_bfloat16 h1 = __float2bfloat16(a - __bfloat162float(h0));
    __nv_bfloat16* row = A + (size_t)(idx >> 10) * KCATA + (idx & 1023);
    row[0] = h0; row[1024] = h1;
}
__global__ __launch_bounds__(256) void split_w_kernel(const float* __restrict__ W1, __nv_bfloat16* __restrict__ B) {
    __shared__ __nv_bfloat16 t0[32][33], t1[32][33];
    const int tx = threadIdx.x, ty = threadIdx.y;   // (32,8)
    const int n0 = blockIdx.x * 32, k0 = blockIdx.y * 32;
#pragma unroll
    for (int i = 0; i < 4; i++) {
        int k = ty + i * 8;
        float w = W1[(size_t)(k0 + k) * HDIM + n0 + tx];
        __nv_bfloat16 h0 = __float2bfloat16(w);
        t0[k][tx] = h0;
        t1[k][tx] = __float2bfloat16(w - __bfloat162float(h0));
    }
    __syncthreads();
#pragma unroll
    for (int i = 0; i < 4; i++) {
        int n = ty + i * 8;
        __nv_bfloat16 b0 = t0[tx][n], b1 = t1[tx][n];
        __nv_bfloat16* row = B + (size_t)(n0 + n) * KCAT + k0 + tx;
        row[0] = b0; row[1024] = b1; row[2048] = b0;
    }
}
// W2 [4096,50] -> W2T [50,4096]
__global__ __launch_bounds__(256) void w2t_kernel(const float* __restrict__ W2, float* __restrict__ W2T) {
    int idx = blockIdx.x * 256 + threadIdx.x;
    int c = idx >> 12, k = idx & 4095;
    W2T[idx] = W2[(size_t)k * NN + c];
}

// ---------------- GEMM1 + fused GEMM2 partials ----------------
// Mainloop: R12-exact (CTA 128x128, warp 64x32, 8 warps, 3 stages, 2 CTA/SM).
// Epilogue: h tile (bias+leaky) -> SMEM; W2T slice -> SMEM; 50-col partial
// GEMM into part[by][m][c]. No g_h traffic, no separate g2split kernel.
#define G1_STAGES 3
#define G1_BKE    64
#define G1_KIT    (KCAT / G1_BKE)   // 48
#define G1_STB    32768
#define G1_SMEM   (G1_STAGES * G1_STB)   // 96KB; epilogue reuse: 128*132+50*132 floats = 94KB

#define HS_STRIDE 132

__global__ __launch_bounds__(256, 2) void gemm1_mma_kernel(
    const __nv_bfloat16* __restrict__ A, const __nv_bfloat16* __restrict__ B,
    const float* __restrict__ bias, const float* __restrict__ W2T,
    float* __restrict__ part)
{
    extern __shared__ char sm[];
    const uint32_t sb = smem_u32(sm);
    const int tid = threadIdx.x, lane = tid & 31, wid = tid >> 5;
    const int m0 = blockIdx.x * 128, n0 = blockIdx.y * 128;
    const int wm = wid >> 2, wn = wid & 3;

    const int lrow = tid >> 1, lhalf = tid & 1;
    const __nv_bfloat16* Ag = A + (size_t)(m0 + lrow) * KCATA + lhalf * 32;
    const __nv_bfloat16* Bg = B + (size_t)(n0 + lrow) * KCAT + lhalf * 32;
    uint32_t swo[4];
#pragma unroll
    for (int j = 0; j < 4; j++) {
        uint32_t o = lrow * 128 + lhalf * 64 + j * 16;
        swo[j] = SW128(o);
    }

#define G1_ISSUE(it) do { \
    const int st_ = (it) % G1_STAGES; \
    const int kea_ = a_chunk(it) * G1_BKE; const int keb_ = (it) * G1_BKE; \
    const uint32_t so_ = sb + st_ * G1_STB; \
    _Pragma("unroll") \
    for (int j = 0; j < 4; j++) { \
        CPA16(so_ + swo[j],         Ag + kea_ + j * 8); \
        CPA16(so_ + 16384 + swo[j], Bg + keb_ + j * 8); \
    } } while (0)

    G1_ISSUE(0); CPA_COMMIT();
    G1_ISSUE(1); CPA_COMMIT();

    float acc[4][4][4];
#pragma unroll
    for (int i = 0; i < 4; i++)
#pragma unroll
        for (int j = 0; j < 4; j++)
#pragma unroll
            for (int q = 0; q < 4; q++) acc[i][j][q] = 0.f;

    const int a_row = wm * 64 + (lane & 7) + 8 * ((lane >> 3) & 1);
    const uint32_t a_kb = (lane >> 4) * 16;
    const int b_row = wn * 32 + (lane & 7) + 8 * (lane >> 4);
    const uint32_t b_kb = ((lane >> 3) & 1) * 16;

    for (int it = 0; it < G1_KIT; it++) {
        CPA_WAIT1();
        __syncthreads();
        if (it + 2 < G1_KIT) G1_ISSUE(it + 2);
        CPA_COMMIT();

        const uint32_t ao = sb + (it % G1_STAGES) * G1_STB;
        const uint32_t bo = ao + 16384;
#pragma unroll
        for (int kk = 0; kk < 4; kk++) {
            uint32_t af[4][4], bf[2][4];
#pragma unroll
            for (int mt = 0; mt < 4; mt++) {
                uint32_t o = (uint32_t)(a_row + mt * 16) * 128 + kk * 32 + a_kb;
                ldm_x4(af[mt], ao + SW128(o));
            }
#pragma unroll
            for (int np = 0; np < 2; np++) {
                uint32_t o = (uint32_t)(b_row + np * 16) * 128 + kk * 32 + b_kb;
                ldm_x4(bf[np], bo + SW128(o));
            }
#pragma unroll
            for (int mt = 0; mt < 4; mt++)
#pragma unroll
                for (int nt = 0; nt < 4; nt++)
                    mma_bf16(acc[mt][nt], af[mt], &bf[nt >> 1][(nt & 1) * 2]);
        }
        __syncthreads();   // phase alignment (R11: removal = 2x slower)
    }

    // ---- fused epilogue ----
    float* hsm = (float*)sm;                    // [128][HS_STRIDE]
    float* wsm = hsm + 128 * HS_STRIDE;         // [50][HS_STRIDE]

    const int erow = lane >> 2, ecol = (lane & 3) * 2;
#pragma unroll
    for (int mt = 0; mt < 4; mt++) {
        const int r0 = wm * 64 + mt * 16 + erow;
#pragma unroll
        for (int nt = 0; nt < 4; nt++) {
            const int c = wn * 32 + nt * 8 + ecol;
            float2 bb = *(const float2*)(bias + n0 + c);
            float v0 = acc[mt][nt][0] + bb.x, v1 = acc[mt][nt][1] + bb.y;
            float v2 = acc[mt][nt][2] + bb.x, v3 = acc[mt][nt][3] + bb.y;
            float2 o0 = { v0 > 0.f ? v0 : 0.01f * v0, v1 > 0.f ? v1 : 0.01f * v1 };
            float2 o1 = { v2 > 0.f ? v2 : 0.01f * v2, v3 > 0.f ? v3 : 0.01f * v3 };
            *(float2*)&hsm[r0 * HS_STRIDE + c] = o0;
            *(float2*)&hsm[(r0 + 8) * HS_STRIDE + c] = o1;
        }
    }
    // W2T slice: 50 rows x 128 k (float4)
    for (int idx = tid; idx < NN * 32; idx += 256) {
        int c = idx >> 5, q = idx & 31;
        *(float4*)&wsm[c * HS_STRIDE + q * 4] =
            *(const float4*)(W2T + (size_t)c * HDIM + n0 + q * 4);
    }
    __syncthreads();

    // partial GEMM2: 160 threads, each 4 rows x 10 cols
    if (tid < 160) {
        const int rg = (tid / 5) * 4;        // 0..124
        const int cg = (tid % 5) * 10;       // 0,10,20,30,40
        float pa[4][10];
#pragma unroll
        for (int i = 0; i < 4; i++)
#pragma unroll
            for (int j = 0; j < 10; j++) pa[i][j] = 0.f;
#pragma unroll 4
        for (int k = 0; k < 128; k += 4) {
            float4 av[4];
#pragma unroll
            for (int i = 0; i < 4; i++) av[i] = *(const float4*)&hsm[(rg + i) * HS_STRIDE + k];
#pragma unroll
            for (int j = 0; j < 10; j++) {
                float4 w = *(const float4*)&wsm[(cg + j) * HS_STRIDE + k];
#pragma unroll
                for (int i = 0; i < 4; i++) {
                    pa[i][j] = fmaf(av[i].x, w.x, pa[i][j]);
                    pa[i][j] = fmaf(av[i].y, w.y, pa[i][j]);
                    pa[i][j] = fmaf(av[i].z, w.z, pa[i][j]);
                    pa[i][j] = fmaf(av[i].w, w.w, pa[i][j]);
                }
            }
        }
        float* pp = part + ((size_t)blockIdx.y * MROWS + m0) * NN;
#pragma unroll
        for (int i = 0; i < 4; i++)
#pragma unroll
            for (int j = 0; j < 10; j++)
                pp[(rg + i) * NN + cg + j] = pa[i][j];
    }
#undef G1_ISSUE
}

// ---------------- Reduce partials + bias/leaky/exp + Sinkhorn --------------
__global__ __launch_bounds__(256) void sinkreduce_kernel(
    const float* __restrict__ part, const float* __restrict__ b2,
    float* __restrict__ P, float* __restrict__ out)
{
    __shared__ float sp[NN * NN];
    const int b = blockIdx.x, tid = threadIdx.x;

    for (int i = tid; i < NN * NN; i += 256) {
        float m = 0.f;
#pragma unroll
        for (int s = 0; s < G2_SLICES; s++)
            m += part[(size_t)s * (MROWS * NN) + b * NN * NN + i];
        m += b2[i % NN];
        m = (m > 0.f) ? m : 0.01f * m;
        sp[i] = expf(m);
    }
    __syncthreads();

    const int warp = tid >> 5, lane = tid & 31;
    for (int it = 0; it < 5; it++) {
        for (int i = warp; i < NN; i += 8) {
            float v0 = sp[i * NN + lane];
            float v1 = (lane + 32 < NN) ? sp[i * NN + lane + 32] : 0.f;
            float s = v0 + v1;
#pragma unroll
            for (int o = 16; o; o >>= 1) s += __shfl_xor_sync(~0u, s, o);
            sp[i * NN + lane] = v0 / s;
            if (lane + 32 < NN) sp[i * NN + lane + 32] = v1 / s;
        }
        __syncthreads();
        for (int j = warp; j < NN; j += 8) {
            float v0 = sp[lane * NN + j];
            float v1 = (lane + 32 < NN) ? sp[(lane + 32) * NN + j] : 0.f;
            float s = v0 + v1;
#pragma unroll
            for (int o = 16; o; o >>= 1) s += __shfl_xor_sync(~0u, s, o);
            sp[lane * NN + j] = v0 / s;
            if (lane + 32 < NN) sp[(lane + 32) * NN + j] = v1 / s;
        }
        __syncthreads();
    }
    float* psi_out = out + PSI_OFF + (size_t)b * NN * NN;
    float* x_out   = out + X_OFF   + (size_t)b * NN * NN;
    float* Pb      = P + (size_t)b * NN * NN;
    for (int i = tid; i < NN * NN; i += 256) {
        float v = sp[i];
        Pb[i] = v; psi_out[i] = v; x_out[i] = v;
    }
}

// ---------------- Hungarian v2 (unchanged) ----------------
__device__ __forceinline__ unsigned long long dsort(double d) {
    long long b = __double_as_longlong(d);
    return (b < 0) ? ~(unsigned long long)b
                   : ((unsigned long long)b | 0x8000000000000000ull);
}

__global__ __launch_bounds__(32) void hungarian_kernel(const float* __restrict__ P, float* __restrict__ out) {
    __shared__ float  sc[NN * NN];
    __shared__ double u_sh[NN + 1];
    __shared__ int    rtc[NN];
    const int b = blockIdx.x, lane = threadIdx.x;
    const double BIG = 1e18;
    const float* Pb = P + (size_t)b * NN * NN;

    for (int i = lane; i < NN * NN; i += 32) sc[i] = Pb[i];
    if (lane <= NN / 2) { u_sh[lane] = 0.0; u_sh[lane + 25] = 0.0; }
    double v0 = 0.0, v1 = 0.0;
    int p0 = 0, p1 = 0;
    const bool has1 = (lane < 18);
    __syncwarp();

    for (int i = 1; i <= NN; i++) {
        bool used0 = false, used1 = !has1;
        double duse0 = 0.0, duse1 = 0.0;
        int way0 = 0, way1 = 0;
        double D = 0.0;
        int j0 = 0;

        while (true) {
            if (j0) {
                if (j0 <= 32) { if (lane == j0 - 1) { used0 = true; duse0 = D; } }
                else          { if (lane == j0 - 33) { used1 = true; duse1 = D; } }
            }
            int i0;
            if (j0 == 0) i0 = i;
            else {
                int pa = __shfl_sync(~0u, p0, (j0 - 1) & 31);
                int pb = __shfl_sync(~0u, p1, (j0 - 33) & 31);
                i0 = (j0 <= 32) ? pa : pb;
            }
            const double ub = u_sh[i0];
            const float* row = sc + (i0 - 1) * NN;
            double c0d = used0 ? BIG : (-(double)row[lane] - ub - v0);
            double c1d = used1 ? BIG : (-(double)row[lane + 32] - ub - v1);

            unsigned long long k0 = (dsort(c0d) & ~63ull) | (unsigned)(lane + 1);
            unsigned long long k1 = (dsort(c1d) & ~63ull) | (unsigned)(lane + 33);
            unsigned long long km = (k0 < k1) ? k0 : k1;
            unsigned hi = (unsigned)(km >> 32);
            unsigned mh = __reduce_min_sync(~0u, hi);
            unsigned lo = (hi == mh) ? (unsigned)km : 0xFFFFFFFFu;
            unsigned ml = __reduce_min_sync(~0u, lo);
            const int j1 = ml & 63;

            double d0 = __shfl_sync(~0u, c0d, (j1 - 1) & 31);
            double d1 = __shfl_sync(~0u, c1d, (j1 - 33) & 31);
            D += (j1 <= 32) ? d0 : d1;

            if (j1 <= 32) { if (lane == j1 - 1) way0 = j0; }
            else          { if (lane == j1 - 33) way1 = j0; }

            int q0 = __shfl_sync(~0u, p0, (j1 - 1) & 31);
            int q1 = __shfl_sync(~0u, p1, (j1 - 33) & 31);
            const int pj1 = (j1 <= 32) ? q0 : q1;
            j0 = j1;
            if (pj1 == 0) break;
        }

        if (used0) { double amt = D - duse0; v0 -= amt; u_sh[p0] += amt; }
        if (has1 && used1) { double amt = D - duse1; v1 -= amt; u_sh[p1] += amt; }
        if (lane == 0) u_sh[i] += D;
        __syncwarp();

        int j = j0;
        while (j) {
            int wa = __shfl_sync(~0u, way0, (j - 1) & 31);
            int wb = __shfl_sync(~0u, way1, (j - 33) & 31);
            int jn = (j <= 32) ? wa : wb;
            int pn;
            if (jn == 0) pn = i;
            else {
                int qa = __shfl_sync(~0u, p0, (jn - 1) & 31);
                int qb = __shfl_sync(~0u, p1, (jn - 33) & 31);
                pn = (jn <= 32) ? qa : qb;
            }
            if (j <= 32) { if (lane == j - 1) p0 = pn; }
            else         { if (lane == j - 33) p1 = pn; }
            j = jn;
        }
    }

    if (p0 > 0) rtc[p0 - 1] = lane;
    if (has1 && p1 > 0) rtc[p1 - 1] = lane + 32;
    __syncwarp();

    float* pb = out + PERM_OFF + (size_t)b * NN * NN;
    for (int i = lane; i < NN * NN; i += 32) pb[i] = 0.f;
    __syncwarp();
    if (lane == 0) {
        float dsum = 0.f;
        for (int r = 0; r < NN; r++) { int c = rtc[r]; pb[r * NN + c] = 1.0f; dsum += sc[r * NN + c]; }
        out[DIST_OFF + b] = dsum / (float)NN;
    }
}

// ---------------------------------------------------------------------------
extern "C" void kernel_launch(void* const* d_in, const int* in_sizes, int n_in,
                              void* d_out, int out_size)
{
    (void)in_sizes; (void)n_in; (void)out_size;
    const float* x  = (const float*)d_in[0];
    const float* W1 = (const float*)d_in[1];
    const float* b1 = (const float*)d_in[2];
    const float* W2 = (const float*)d_in[3];
    const float* b2 = (const float*)d_in[4];
    float* out = (float*)d_out;

    float* P;   cudaGetSymbolAddress((void**)&P,   g_P);
    float* pt;  cudaGetSymbolAddress((void**)&pt,  g_part);
    float* w2t; cudaGetSymbolAddress((void**)&w2t, g_W2T);
    __nv_bfloat16* Ac; cudaGetSymbolAddress((void**)&Ac, g_Acat);
    __nv_bfloat16* Bc; cudaGetSymbolAddress((void**)&Bc, g_Bcat);

    cudaFuncSetAttribute(gemm1_mma_kernel, cudaFuncAttributeMaxDynamicSharedMemorySize, G1_SMEM);

    split_x_kernel<<<MROWS * FDIM / 256, 256>>>(x, Ac);
    split_w_kernel<<<dim3(HDIM / 32, FDIM / 32), dim3(32, 8)>>>(W1, Bc);
    w2t_kernel<<<NN * HDIM / 256, 256>>>(W2, w2t);
    gemm1_mma_kernel<<<dim3(MROWS / 128, HDIM / 128), 256, G1_SMEM>>>(Ac, Bc, b1, w2t, pt);
    sinkreduce_kernel<<<BATCH, 256>>>(pt, b2, P, out);
    hungarian_kernel<<<BATCH, 32>>>(P, out);
}

// round 16
// speedup vs baseline: 1.3250x; 1.0203x over previous
#include <cuda_runtime.h>
#include <cuda_bf16.h>
#include <math.h>
#include <stdint.h>

#define BATCH 128
#define NN    50
#define FDIM  1024
#define HDIM  4096
#define MROWS (BATCH*NN)
#define KCAT  (3*FDIM)          // logical 3072: A slots [a0,a0,a1], B slots [b0,b1,b0]
#define KCATA (2*FDIM)          // stored A: [a0,a1]

#define PSI_OFF  0
#define PERM_OFF (BATCH*NN*NN)
#define X_OFF    (2*BATCH*NN*NN)
#define DIST_OFF (3*BATCH*NN*NN)

#define G2_SLICES 16
#define G2_KS     (HDIM / G2_SLICES)   // 256

__device__ float         g_h[(size_t)MROWS * HDIM];
__device__ float         g_part[(size_t)G2_SLICES * BATCH * NN * NN];
__device__ float         g_W2T[(size_t)NN * HDIM];
__device__ __nv_bfloat16 g_Acat[(size_t)MROWS * KCATA];
__device__ __nv_bfloat16 g_Bcat[(size_t)HDIM * KCAT];

__device__ __forceinline__ uint32_t smem_u32(const void* p) {
    uint32_t a;
    asm("{ .reg .u64 t; cvta.to.shared.u64 t, %1; cvt.u32.u64 %0, t; }" : "=r"(a) : "l"(p));
    return a;
}
#define SW128(o) ((o) ^ (((o) >> 3) & 0x70))
#define CPA16(dst, src) asm volatile("cp.async.cg.shared.global [%0], [%1], 16;" :: "r"(dst), "l"(src) : "memory")
#define CPA_COMMIT()    asm volatile("cp.async.commit_group;" ::: "memory")
#define CPA_WAIT1()     asm volatile("cp.async.wait_group 1;" ::: "memory")

__device__ __forceinline__ void ldm_x4(uint32_t* r, uint32_t addr) {
    asm volatile("ldmatrix.sync.aligned.m8n8.x4.shared.b16 {%0,%1,%2,%3}, [%4];"
        : "=r"(r[0]), "=r"(r[1]), "=r"(r[2]), "=r"(r[3]) : "r"(addr));
}
__device__ __forceinline__ void mma_bf16(float* d, const uint32_t* a, const uint32_t* b) {
    asm volatile("mma.sync.aligned.m16n8k16.row.col.f32.bf16.bf16.f32 "
        "{%0,%1,%2,%3}, {%4,%5,%6,%7}, {%8,%9}, {%0,%1,%2,%3};"
        : "+f"(d[0]), "+f"(d[1]), "+f"(d[2]), "+f"(d[3])
        : "r"(a[0]), "r"(a[1]), "r"(a[2]), "r"(a[3]), "r"(b[0]), "r"(b[1]));
}

__device__ __forceinline__ int a_chunk(int c) {
    return (c & 15) + ((c >= 32) ? 16 : 0);
}

// ---------------- split kernels (2-term bf16 split) ----------------
__global__ __launch_bounds__(256) void split_x_kernel(const float* __restrict__ x, __nv_bfloat16* __restrict__ A) {
    int idx = blockIdx.x * 256 + threadIdx.x;
    float a = x[idx];
    __nv_bfloat16 h0 = __float2bfloat16(a);
    __nv_bfloat16 h1 = __float2bfloat16(a - __bfloat162float(h0));
    __nv_bfloat16* row = A + (size_t)(idx >> 10) * KCATA + (idx & 1023);
    row[0] = h0; row[1024] = h1;
}
__global__ __launch_bounds__(256) void split_w_kernel(const float* __restrict__ W1, __nv_bfloat16* __restrict__ B) {
    __shared__ __nv_bfloat16 t0[32][33], t1[32][33];
    const int tx = threadIdx.x, ty = threadIdx.y;   // (32,8)
    const int n0 = blockIdx.x * 32, k0 = blockIdx.y * 32;
#pragma unroll
    for (int i = 0; i < 4; i++) {
        int k = ty + i * 8;
        float w = W1[(size_t)(k0 + k) * HDIM + n0 + tx];
        __nv_bfloat16 h0 = __float2bfloat16(w);
        t0[k][tx] = h0;
        t1[k][tx] = __float2bfloat16(w - __bfloat162float(h0));
    }
    __syncthreads();
#pragma unroll
    for (int i = 0; i < 4; i++) {
        int n = ty + i * 8;
        __nv_bfloat16 b0 = t0[tx][n], b1 = t1[tx][n];
        __nv_bfloat16* row = B + (size_t)(n0 + n) * KCAT + k0 + tx;
        row[0] = b0; row[1024] = b1; row[2048] = b0;
    }
}
// W2 [4096,50] -> W2T [50,4096]
__global__ __launch_bounds__(256) void w2t_kernel(const float* __restrict__ W2, float* __restrict__ W2T) {
    int idx = blockIdx.x * 256 + threadIdx.x;
    int c = idx >> 12, k = idx & 4095;
    W2T[idx] = W2[(size_t)k * NN + c];
}

// ---------------- GEMM1: mma.sync bf16 (R12-exact config) ----------------
#define G1_STAGES 3
#define G1_BKE    64
#define G1_KIT    (KCAT / G1_BKE)   // 48
#define G1_STB    32768
#define G1_SMEM   (G1_STAGES * G1_STB)

__global__ __launch_bounds__(256, 2) void gemm1_mma_kernel(
    const __nv_bfloat16* __restrict__ A, const __nv_bfloat16* __restrict__ B,
    const float* __restrict__ bias, float* __restrict__ C)
{
    extern __shared__ char sm[];
    const uint32_t sb = smem_u32(sm);
    const int tid = threadIdx.x, lane = tid & 31, wid = tid >> 5;
    const int m0 = blockIdx.x * 128, n0 = blockIdx.y * 128;
    const int wm = wid >> 2, wn = wid & 3;

    const int lrow = tid >> 1, lhalf = tid & 1;
    const __nv_bfloat16* Ag = A + (size_t)(m0 + lrow) * KCATA + lhalf * 32;
    const __nv_bfloat16* Bg = B + (size_t)(n0 + lrow) * KCAT + lhalf * 32;
    uint32_t swo[4];
#pragma unroll
    for (int j = 0; j < 4; j++) {
        uint32_t o = lrow * 128 + lhalf * 64 + j * 16;
        swo[j] = SW128(o);
    }

#define G1_ISSUE(it) do { \
    const int st_ = (it) % G1_STAGES; \
    const int kea_ = a_chunk(it) * G1_BKE; const int keb_ = (it) * G1_BKE; \
    const uint32_t so_ = sb + st_ * G1_STB; \
    _Pragma("unroll") \
    for (int j = 0; j < 4; j++) { \
        CPA16(so_ + swo[j],         Ag + kea_ + j * 8); \
        CPA16(so_ + 16384 + swo[j], Bg + keb_ + j * 8); \
    } } while (0)

    G1_ISSUE(0); CPA_COMMIT();
    G1_ISSUE(1); CPA_COMMIT();

    float acc[4][4][4];
#pragma unroll
    for (int i = 0; i < 4; i++)
#pragma unroll
        for (int j = 0; j < 4; j++)
#pragma unroll
            for (int q = 0; q < 4; q++) acc[i][j][q] = 0.f;

    const int a_row = wm * 64 + (lane & 7) + 8 * ((lane >> 3) & 1);
    const uint32_t a_kb = (lane >> 4) * 16;
    const int b_row = wn * 32 + (lane & 7) + 8 * (lane >> 4);
    const uint32_t b_kb = ((lane >> 3) & 1) * 16;

    for (int it = 0; it < G1_KIT; it++) {
        CPA_WAIT1();
        __syncthreads();
        if (it + 2 < G1_KIT) G1_ISSUE(it + 2);
        CPA_COMMIT();

        const uint32_t ao = sb + (it % G1_STAGES) * G1_STB;
        const uint32_t bo = ao + 16384;
#pragma unroll
        for (int kk = 0; kk < 4; kk++) {
            uint32_t af[4][4], bf[2][4];
#pragma unroll
            for (int mt = 0; mt < 4; mt++) {
                uint32_t o = (uint32_t)(a_row + mt * 16) * 128 + kk * 32 + a_kb;
                ldm_x4(af[mt], ao + SW128(o));
            }
#pragma unroll
            for (int np = 0; np < 2; np++) {
                uint32_t o = (uint32_t)(b_row + np * 16) * 128 + kk * 32 + b_kb;
                ldm_x4(bf[np], bo + SW128(o));
            }
#pragma unroll
            for (int mt = 0; mt < 4; mt++)
#pragma unroll
                for (int nt = 0; nt < 4; nt++)
                    mma_bf16(acc[mt][nt], af[mt], &bf[nt >> 1][(nt & 1) * 2]);
        }
        __syncthreads();   // phase alignment (R11: removal = 2x slower)
    }

    const int erow = lane >> 2, ecol = (lane & 3) * 2;
#pragma unroll
    for (int mt = 0; mt < 4; mt++) {
        const int r0 = m0 + wm * 64 + mt * 16 + erow;
#pragma unroll
        for (int nt = 0; nt < 4; nt++) {
            const int c = n0 + wn * 32 + nt * 8 + ecol;
            float2 bb = *(const float2*)(bias + c);
            float v0 = acc[mt][nt][0] + bb.x, v1 = acc[mt][nt][1] + bb.y;
            float v2 = acc[mt][nt][2] + bb.x, v3 = acc[mt][nt][3] + bb.y;
            float2 o0 = { v0 > 0.f ? v0 : 0.01f * v0, v1 > 0.f ? v1 : 0.01f * v1 };
            float2 o1 = { v2 > 0.f ? v2 : 0.01f * v2, v3 > 0.f ? v3 : 0.01f * v3 };
            *(float2*)(C + (size_t)r0 * HDIM + c) = o0;
            *(float2*)(C + (size_t)(r0 + 8) * HDIM + c) = o1;
        }
    }
#undef G1_ISSUE
}

// ---------------- GEMM2 split-K (R12-exact) ----------------
__global__ __launch_bounds__(128) void g2split_kernel(
    const float* __restrict__ h, const float* __restrict__ W2T,
    float* __restrict__ part)
{
    __shared__ float hs[NN][68];
    __shared__ float ws[NN][68];
    const int b = blockIdx.x, s = blockIdx.y, tid = threadIdx.x;
    const int kbase = s * G2_KS;
    const float* hb = h + (size_t)b * NN * HDIM + kbase;

    const int r0 = (tid / 10) * 5, c0 = (tid % 10) * 5;   // tid<100
    float acc[5][5];
#pragma unroll
    for (int i = 0; i < 5; i++)
#pragma unroll
        for (int j = 0; j < 5; j++) acc[i][j] = 0.f;

    for (int kc = 0; kc < G2_KS; kc += 64) {
        __syncthreads();
        for (int idx = tid; idx < NN * 16; idx += 128) {
            int r = idx >> 4, q = idx & 15;
            *(float4*)&hs[r][q * 4] = *(const float4*)(hb + (size_t)r * HDIM + kc + q * 4);
            *(float4*)&ws[r][q * 4] = *(const float4*)(W2T + (size_t)r * HDIM + kbase + kc + q * 4);
        }
        __syncthreads();
        if (tid < 100) {
#pragma unroll
            for (int k = 0; k < 64; k += 4) {
                float4 a[5];
#pragma unroll
                for (int i = 0; i < 5; i++) a[i] = *(const float4*)&hs[r0 + i][k];
#pragma unroll
                for (int j = 0; j < 5; j++) {
                    float4 w = *(const float4*)&ws[c0 + j][k];
#pragma unroll
                    for (int i = 0; i < 5; i++) {
                        acc[i][j] = fmaf(a[i].x, w.x, acc[i][j]);
                        acc[i][j] = fmaf(a[i].y, w.y, acc[i][j]);
                        acc[i][j] = fmaf(a[i].z, w.z, acc[i][j]);
                        acc[i][j] = fmaf(a[i].w, w.w, acc[i][j]);
                    }
                }
            }
        }
    }
    if (tid < 100) {
        float* pp = part + ((size_t)s * BATCH + b) * NN * NN;
#pragma unroll
        for (int i = 0; i < 5; i++)
#pragma unroll
            for (int j = 0; j < 5; j++)
                pp[(r0 + i) * NN + c0 + j] = acc[i][j];
    }
}

// ---------------- Fused: reduce + Sinkhorn + Hungarian ----------------
// Phase 1 (256 thr): sum partials, bias/leaky/exp, 5 Sinkhorn iters, write psi/X.
// Phase 2 (warp 0): buggy-greedy Hungarian on psi in SMEM (p/way in SMEM,
// deferred u/v potentials; arithmetic identical to the R12 hungarian).
__device__ __forceinline__ unsigned long long dsort(double d) {
    long long b = __double_as_longlong(d);
    return (b < 0) ? ~(unsigned long long)b
                   : ((unsigned long long)b | 0x8000000000000000ull);
}

__global__ __launch_bounds__(256) void sinkhung_kernel(
    const float* __restrict__ part, const float* __restrict__ b2,
    float* __restrict__ out)
{
    __shared__ float  sp[NN * NN];
    __shared__ double u_sh[NN + 1];
    __shared__ int    p_sh[NN + 1], way_sh[NN + 1];
    __shared__ int    rtc[NN];
    const int b = blockIdx.x, tid = threadIdx.x;

    for (int i = tid; i < NN * NN; i += 256) {
        float m = 0.f;
#pragma unroll
        for (int s = 0; s < G2_SLICES; s++)
            m += part[((size_t)s * BATCH + b) * NN * NN + i];
        m += b2[i % NN];
        m = (m > 0.f) ? m : 0.01f * m;
        sp[i] = expf(m);
    }
    __syncthreads();

    const int warp = tid >> 5, lane = tid & 31;
    for (int it = 0; it < 5; it++) {
        for (int i = warp; i < NN; i += 8) {
            float v0 = sp[i * NN + lane];
            float v1 = (lane + 32 < NN) ? sp[i * NN + lane + 32] : 0.f;
            float s = v0 + v1;
#pragma unroll
            for (int o = 16; o; o >>= 1) s += __shfl_xor_sync(~0u, s, o);
            sp[i * NN + lane] = v0 / s;
            if (lane + 32 < NN) sp[i * NN + lane + 32] = v1 / s;
        }
        __syncthreads();
        for (int j = warp; j < NN; j += 8) {
            float v0 = sp[lane * NN + j];
            float v1 = (lane + 32 < NN) ? sp[(lane + 32) * NN + j] : 0.f;
            float s = v0 + v1;
#pragma unroll
            for (int o = 16; o; o >>= 1) s += __shfl_xor_sync(~0u, s, o);
            sp[lane * NN + j] = v0 / s;
            if (lane + 32 < NN) sp[(lane + 32) * NN + j] = v1 / s;
        }
        __syncthreads();
    }
    {
        float* psi_out = out + PSI_OFF + (size_t)b * NN * NN;
        float* x_out   = out + X_OFF   + (size_t)b * NN * NN;
        for (int i = tid; i < NN * NN; i += 256) {
            float v = sp[i];
            psi_out[i] = v; x_out[i] = v;
        }
    }
    __syncthreads();

    if (warp != 0) return;

    // ---- Hungarian (warp 0 only), psi already in sp ----
    const double BIG = 1e18;
    for (int j = lane; j <= NN; j += 32) { p_sh[j] = 0; }
    if (lane <= NN / 2) { u_sh[lane] = 0.0; u_sh[lane + 25] = 0.0; }
    double v0 = 0.0, v1 = 0.0;
    const bool has1 = (lane < 18);
    __syncwarp();

    for (int i = 1; i <= NN; i++) {
        if (lane == 0) p_sh[0] = i;
        bool used0 = false, used1 = !has1;
        double duse0 = 0.0, duse1 = 0.0;
        double D = 0.0;
        int j0 = 0;
        __syncwarp();

        while (true) {
            if (j0) {
                if (j0 <= 32) { if (lane == j0 - 1) { used0 = true; duse0 = D; } }
                else          { if (lane == j0 - 33) { used1 = true; duse1 = D; } }
            }
            const int i0 = p_sh[j0];               // broadcast LDS
            const double ub = u_sh[i0];
            const float* row = sp + (i0 - 1) * NN;
            double c0d = used0 ? BIG : (-(double)row[lane] - ub - v0);
            double c1d = used1 ? BIG : (-(double)row[lane + 32] - ub - v1);

            unsigned long long k0 = (dsort(c0d) & ~63ull) | (unsigned)(lane + 1);
            unsigned long long k1 = (dsort(c1d) & ~63ull) | (unsigned)(lane + 33);
            unsigned long long km = (k0 < k1) ? k0 : k1;
            unsigned hi = (unsigned)(km >> 32);
            unsigned mh = __reduce_min_sync(~0u, hi);
            unsigned lo = (hi == mh) ? (unsigned)km : 0xFFFFFFFFu;
            unsigned ml = __reduce_min_sync(~0u, lo);
            const int j1 = ml & 63;

            double d0 = __shfl_sync(~0u, c0d, (j1 - 1) & 31);
            double d1 = __shfl_sync(~0u, c1d, (j1 - 33) & 31);
            D += (j1 <= 32) ? d0 : d1;

            if (lane == 0) way_sh[j1] = j0;
            const int pj1 = p_sh[j1];              // broadcast LDS (pre-rotation value)
            j0 = j1;
            if (pj1 == 0) break;
        }

        // deferred u/v updates (pre-rotation p; distinct rows per used col)
        if (used0) { double amt = D - duse0; v0 -= amt; u_sh[p_sh[lane + 1]] += amt; }
        if (has1 && used1) { double amt = D - duse1; v1 -= amt; u_sh[p_sh[lane + 33]] += amt; }
        if (lane == 0) u_sh[i] += D;
        __syncwarp();

        // rotate matching along chain (serial, lane 0)
        if (lane == 0) {
            int j = j0;
            while (j) { int jn = way_sh[j]; p_sh[j] = p_sh[jn]; j = jn; }
        }
        __syncwarp();
    }

    {
        int j = lane + 1;
        int pv = p_sh[j];
        if (pv > 0) rtc[pv - 1] = j - 1;
        j = lane + 33;
        if (j <= NN) { pv = p_sh[j]; if (pv > 0) rtc[pv - 1] = j - 1; }
    }
    __syncwarp();

    float* pb = out + PERM_OFF + (size_t)b * NN * NN;
    for (int i = lane; i < NN * NN; i += 32) pb[i] = 0.f;
    __syncwarp();
    if (lane == 0) {
        float dsum = 0.f;
        for (int r = 0; r < NN; r++) { int c = rtc[r]; pb[r * NN + c] = 1.0f; dsum += sp[r * NN + c]; }
        out[DIST_OFF + b] = dsum / (float)NN;
    }
}

// ---------------------------------------------------------------------------
extern "C" void kernel_launch(void* const* d_in, const int* in_sizes, int n_in,
                              void* d_out, int out_size)
{
    (void)in_sizes; (void)n_in; (void)out_size;
    const float* x  = (const float*)d_in[0];
    const float* W1 = (const float*)d_in[1];
    const float* b1 = (const float*)d_in[2];
    const float* W2 = (const float*)d_in[3];
    const float* b2 = (const float*)d_in[4];
    float* out = (float*)d_out;

    float* h;   cudaGetSymbolAddress((void**)&h,   g_h);
    float* pt;  cudaGetSymbolAddress((void**)&pt,  g_part);
    float* w2t; cudaGetSymbolAddress((void**)&w2t, g_W2T);
    __nv_bfloat16* Ac; cudaGetSymbolAddress((void**)&Ac, g_Acat);
    __nv_bfloat16* Bc; cudaGetSymbolAddress((void**)&Bc, g_Bcat);

    cudaFuncSetAttribute(gemm1_mma_kernel, cudaFuncAttributeMaxDynamicSharedMemorySize, G1_SMEM);

    split_x_kernel<<<MROWS * FDIM / 256, 256>>>(x, Ac);
    split_w_kernel<<<dim3(HDIM / 32, FDIM / 32), dim3(32, 8)>>>(W1, Bc);
    w2t_kernel<<<NN * HDIM / 256, 256>>>(W2, w2t);
    gemm1_mma_kernel<<<dim3(MROWS / 128, HDIM / 128), 256, G1_SMEM>>>(Ac, Bc, b1, h);
    g2split_kernel<<<dim3(BATCH, G2_SLICES), 128>>>(h, w2t, pt);
    sinkhung_kernel<<<BATCH, 256>>>(pt, b2, out);
}